// round 17
// baseline (speedup 1.0000x reference)
#include <cuda_runtime.h>
#include <math.h>

// ChamferLoss fused-symmetric: both directions share dot products.
// d2(m,n) = 2*(hp_m + hg_n - p.g);  row_min_m = min_n (hg_n - p.g),
// col_min_n = min_m (hp_m - p.g);  fwd uses 2*(hp+rowmin), bwd 2*(hg+colmin).
//
// 1024 blocks x 128 threads = (8 m-tiles x 32 n-chunks) x 4 batch.
//  - smem: 128 gt points as interleaved f32x2 records {x2,y2,z2,hg2} (2 KB)
//  - QPT=4 m-queries/thread; per record: dot2 (mul2+2 fma2) shared by both
//    directions; row mins in registers; col mins via register tournament +
//    shfl-bfly warp reduce + smem cross-warp combine
//  - row combine: last-4 blocks of each (b,tile) group, 128 queries each
//  - col combine: last block of each (b,chunk) group, 128 n's
//  - final: last of 256 partial writers sums fixed-order -> out
// Counters self-reset for graph replay; all sums fixed-order/deterministic.

#define BATCH   4
#define NPTS    4096
#define THREADS 128
#define QPT     4
#define MTILE   (THREADS * QPT)          // 512 queries per tile
#define NMT     (NPTS / MTILE)           // 8 m-tiles
#define NCHN    128                      // gt points per chunk
#define NCHUNKS (NPTS / NCHN)            // 32 n-chunks
#define RECS    (NCHN / 2)               // 64 2-point records
#define RGROUPS (BATCH * NMT)            // 32 row groups (x32 blocks each)
#define CGROUPS (BATCH * NCHUNKS)        // 128 col groups (x8 blocks each)
#define RCOMB   4                        // last-4 split the row combine
#define NPART   (RGROUPS * RCOMB + CGROUPS)   // 128 + 128 = 256

__device__ float g_srow[BATCH * NMT * NCHUNKS * MTILE];   // 2 MB
__device__ float g_scol[BATCH * NCHUNKS * NMT * NCHN];    // 512 KB
__device__ float g_partials[NPART];
__device__ int   g_cnt_row[RGROUPS];     // zero-init; self-resetting
__device__ int   g_cnt_col[CGROUPS];     // zero-init; self-resetting
__device__ int   g_fin;                  // zero-init; self-resetting

__device__ __forceinline__ unsigned long long pack2(float lo, float hi) {
    unsigned long long r;
    asm("mov.b64 %0, {%1, %2};" : "=l"(r) : "f"(lo), "f"(hi));
    return r;
}
__device__ __forceinline__ void unpack2(unsigned long long v, float& lo, float& hi) {
    asm("mov.b64 {%0, %1}, %2;" : "=f"(lo), "=f"(hi) : "l"(v));
}
__device__ __forceinline__ unsigned long long fma2(unsigned long long a,
                                                   unsigned long long b,
                                                   unsigned long long c) {
    unsigned long long d;
    asm("fma.rn.f32x2 %0, %1, %2, %3;" : "=l"(d) : "l"(a), "l"(b), "l"(c));
    return d;
}
__device__ __forceinline__ unsigned long long mul2(unsigned long long a,
                                                   unsigned long long b) {
    unsigned long long d;
    asm("mul.rn.f32x2 %0, %1, %2;" : "=l"(d) : "l"(a), "l"(b));
    return d;
}
__device__ __forceinline__ unsigned long long add2(unsigned long long a,
                                                   unsigned long long b) {
    unsigned long long d;
    asm("add.rn.f32x2 %0, %1, %2;" : "=l"(d) : "l"(a), "l"(b));
    return d;
}

__global__ __launch_bounds__(THREADS, 7)
void chamfer_fused(const float* __restrict__ predict,
                   const float* __restrict__ gt,
                   float* __restrict__ out) {
    const int tile  = blockIdx.x >> 5;     // 0..7   m-tile (512 queries)
    const int chunk = blockIdx.x & 31;     // 0..31  n-chunk (128 gt points)
    const int b     = blockIdx.z;
    const int tid   = threadIdx.x;
    const int warp  = tid >> 5;
    const int lane  = tid & 31;
    const int base  = b * 3 * NPTS;
    const int rgroup = b * NMT + tile;
    const int cgroup = b * NCHUNKS + chunk;
    const float SCALE = 1.0f / (float)(BATCH * NPTS);

    __shared__ float sdb[NCHN * 4];            // interleaved records (2 KB)
    __shared__ float scol[4][NCHN];            // per-warp col mins (2 KB)
    __shared__ float red[THREADS];
    __shared__ int   sh_rrank, sh_cdo, sh_fin;

    // Load gt chunk -> smem records {gx0,gx1, gy0,gy1, gz0,gz1, hg0,hg1}
    if (tid < NCHN) {
        const int n  = chunk * NCHN + tid;
        const float gx = gt[base + 0 * NPTS + n];
        const float gy = gt[base + 1 * NPTS + n];
        const float gz = gt[base + 2 * NPTS + n];
        const float hg = 0.5f * fmaf(gx, gx, fmaf(gy, gy, gz * gz));
        const int j = tid >> 1, l = tid & 1;
        sdb[j * 8 + 0 + l] = gx;
        sdb[j * 8 + 2 + l] = gy;
        sdb[j * 8 + 4 + l] = gz;
        sdb[j * 8 + 6 + l] = hg;
    }
    __syncthreads();

    // 4 predict queries per thread (negated coords; hp = 0.5|p|^2)
    unsigned long long qx2[QPT], qy2[QPT], qz2[QPT], hp2[QPT];
    #pragma unroll
    for (int jq = 0; jq < QPT; ++jq) {
        const int m = tile * MTILE + jq * THREADS + tid;
        const float px = predict[base + 0 * NPTS + m];
        const float py = predict[base + 1 * NPTS + m];
        const float pz = predict[base + 2 * NPTS + m];
        const float hp = 0.5f * fmaf(px, px, fmaf(py, py, pz * pz));
        qx2[jq] = pack2(-px, -px);
        qy2[jq] = pack2(-py, -py);
        qz2[jq] = pack2(-pz, -pz);
        hp2[jq] = pack2(hp, hp);
    }

    float mnA[QPT], mnB[QPT];
    #pragma unroll
    for (int jq = 0; jq < QPT; ++jq) { mnA[jq] = 3.4e38f; mnB[jq] = 3.4e38f; }

    const ulonglong2* s2 = (const ulonglong2*)sdb;
    #pragma unroll 2
    for (int r = 0; r < RECS; ++r) {
        const ulonglong2 A = s2[2 * r + 0];   // {x0,x1},{y0,y1}
        const ulonglong2 B = s2[2 * r + 1];   // {z0,z1},{hg0,hg1}
        float clo = 3.4e38f, chi = 3.4e38f;
        #pragma unroll
        for (int jq = 0; jq < QPT; ++jq) {
            const unsigned long long dot2 =
                fma2(qz2[jq], B.x, fma2(qy2[jq], A.y, mul2(qx2[jq], A.x)));
            // forward: hg - p.g
            float rlo, rhi;
            unpack2(add2(B.y, dot2), rlo, rhi);
            mnA[jq] = fminf(mnA[jq], rlo);
            mnB[jq] = fminf(mnB[jq], rhi);
            // backward: hp - p.g
            float vlo, vhi;
            unpack2(add2(hp2[jq], dot2), vlo, vhi);
            clo = fminf(clo, vlo);
            chi = fminf(chi, vhi);
        }
        // warp reduce col mins (all-lanes bfly), lane0 stores
        #pragma unroll
        for (int off = 16; off > 0; off >>= 1) {
            clo = fminf(clo, __shfl_xor_sync(0xFFFFFFFFu, clo, off));
            chi = fminf(chi, __shfl_xor_sync(0xFFFFFFFFu, chi, off));
        }
        if (lane == 0) {
            scol[warp][2 * r + 0] = clo;
            scol[warp][2 * r + 1] = chi;
        }
    }

    // Row mins -> global scratch
    const int rbase = (rgroup * NCHUNKS + chunk) * MTILE;
    #pragma unroll
    for (int jq = 0; jq < QPT; ++jq)
        g_srow[rbase + jq * THREADS + tid] = fminf(mnA[jq], mnB[jq]);

    // Cross-warp col mins -> global scratch (one n per thread)
    __syncthreads();
    {
        const float v = fminf(fminf(scol[0][tid], scol[1][tid]),
                              fminf(scol[2][tid], scol[3][tid]));
        g_scol[(cgroup * NMT + tile) * NCHN + tid] = v;
    }

    // ---- tickets ----
    __threadfence();
    if (tid == 0) {
        const int rp = atomicAdd(&g_cnt_row[rgroup], 1);
        sh_rrank = rp - (NCHUNKS - RCOMB);            // >=0: row combiner
        if (rp == NCHUNKS - 1) g_cnt_row[rgroup] = 0;
        const int cp = atomicAdd(&g_cnt_col[cgroup], 1);
        sh_cdo = (cp == NMT - 1) ? 1 : 0;             // col combiner
        if (sh_cdo) g_cnt_col[cgroup] = 0;
        sh_fin = 0;
    }
    __syncthreads();
    const int rrank = sh_rrank;
    const int cdo   = sh_cdo;
    if (rrank < 0 && !cdo) return;
    __threadfence();

    // ---- col combine: 128 n's, min over 8 tiles, bwd contribution ----
    if (cdo) {
        const int cb = cgroup * NMT * NCHN + tid;
        float s = g_scol[cb];
        #pragma unroll
        for (int t = 1; t < NMT; ++t)
            s = fminf(s, g_scol[cb + t * NCHN]);
        const int n  = chunk * NCHN + tid;
        const float gx = gt[base + 0 * NPTS + n];
        const float gy = gt[base + 1 * NPTS + n];
        const float gz = gt[base + 2 * NPTS + n];
        const float hg = 0.5f * fmaf(gx, gx, fmaf(gy, gy, gz * gz));
        const float d2 = fmaxf(2.0f * (hg + s), 0.0f);
        float acc = sqrtf(d2 + 1e-8f) * SCALE;

        red[tid] = acc;
        __syncthreads();
        if (tid < 64) red[tid] += red[tid + 64];
        __syncthreads();
        if (tid < 32) {
            float v = red[tid] + red[tid + 32];
            #pragma unroll
            for (int off = 16; off > 0; off >>= 1)
                v += __shfl_down_sync(0xFFFFFFFFu, v, off);
            if (tid == 0) {
                g_partials[RGROUPS * RCOMB + cgroup] = v;
                __threadfence();
                const int prev = atomicAdd(&g_fin, 1);
                if (prev == NPART - 1) { g_fin = 0; sh_fin = 1; }
            }
        }
        __syncthreads();
    }

    // ---- row combine: 128 queries (quarter), min over 32 chunks, fwd ----
    if (rrank >= 0) {
        const int ql = rrank * (MTILE / RCOMB) + tid;   // 0..511
        const int rb = rgroup * NCHUNKS * MTILE;
        float s = g_srow[rb + ql];
        #pragma unroll
        for (int c = 1; c < NCHUNKS; ++c)
            s = fminf(s, g_srow[rb + c * MTILE + ql]);
        const int m = tile * MTILE + ql;
        const float px = predict[base + 0 * NPTS + m];
        const float py = predict[base + 1 * NPTS + m];
        const float pz = predict[base + 2 * NPTS + m];
        const float hp = 0.5f * fmaf(px, px, fmaf(py, py, pz * pz));
        const float d2 = fmaxf(2.0f * (hp + s), 0.0f);
        float acc = sqrtf(d2 + 1e-8f) * SCALE;

        red[tid] = acc;
        __syncthreads();
        if (tid < 64) red[tid] += red[tid + 64];
        __syncthreads();
        if (tid < 32) {
            float v = red[tid] + red[tid + 32];
            #pragma unroll
            for (int off = 16; off > 0; off >>= 1)
                v += __shfl_down_sync(0xFFFFFFFFu, v, off);
            if (tid == 0) {
                g_partials[rgroup * RCOMB + rrank] = v;
                __threadfence();
                const int prev = atomicAdd(&g_fin, 1);
                if (prev == NPART - 1) { g_fin = 0; sh_fin = 1; }
            }
        }
        __syncthreads();
    }

    // ---- final: fixed-order sum of 256 partials ----
    if (sh_fin) {
        __threadfence();
        float v = g_partials[tid] + g_partials[tid + THREADS];
        red[tid] = v;
        __syncthreads();
        if (tid < 64) red[tid] += red[tid + 64];
        __syncthreads();
        if (tid < 32) {
            float w = red[tid] + red[tid + 32];
            #pragma unroll
            for (int off = 16; off > 0; off >>= 1)
                w += __shfl_down_sync(0xFFFFFFFFu, w, off);
            if (tid == 0) out[0] = w;
        }
    }
}

extern "C" void kernel_launch(void* const* d_in, const int* in_sizes, int n_in,
                              void* d_out, int out_size) {
    const float* predict = (const float*)d_in[0];
    const float* gt      = (const float*)d_in[1];
    float* out = (float*)d_out;

    dim3 grid(NMT * NCHUNKS, 1, BATCH);   // 256 x 1 x 4 = 1024 blocks
    chamfer_fused<<<grid, THREADS>>>(predict, gt, out);
}